// round 13
// baseline (speedup 1.0000x reference)
#include <cuda_runtime.h>
#include <cstdint>

// TSBRNN: B=8192 rows, T=4096, per-row 2-state swap recurrence.
// R13 = R12 with a 2-stage ring (smem 208KB -> 144KB). R12 hit the DRAM
// floor in kernel time (ncu 42.2us, 71% DRAM) but wallclock-ncu gap grew to
// ~12us; across rounds the gap tracks smem > ~180KB. 2 tiles in flight per
// warp (16KB) still covers DRAM latency (tile period ~2000cyc >> 577cyc).

namespace {
constexpr int T_LEN   = 4096;
constexpr int TT      = 64;               // timesteps per tile
constexpr int WROWS   = 32;               // rows per warp (1 row/lane)
constexpr int WARPS   = 8;                // 2 rowgroups x 4 chunks
constexpr int THREADS = 32 * WARPS;       // 256
constexpr int ROWS    = 64;               // rows per CTA -> grid 128 (one wave)
constexpr int STAGES  = 2;
constexpr int TILE_F  = WROWS * TT;       // 2048 floats = 8KB per stage
constexpr int WIN_F   = STAGES * TILE_F;  // 16KB ring per warp
constexpr int SMEM_FLOATS = WARPS * WIN_F + T_LEN;
constexpr int SMEM_BYTES  = SMEM_FLOATS * 4;   // 128KB + 16KB = 144KB
constexpr int WARM       = 256;           // warmup steps, chunks 1-3 (4 tiles)
constexpr int N_TILES    = 19;            // uniform tiles per warp
constexpr int WARM_TILES = WARM / TT;     // 4
__constant__ int CHUNK_START_C[4] = {0, 1216, 2176, 3136};
}

__device__ __forceinline__ void cp_async16(uint32_t dst, const void* src) {
    asm volatile("cp.async.cg.shared.global [%0], [%1], 16;\n" :: "r"(dst), "l"(src));
}
__device__ __forceinline__ void cp_commit() {
    asm volatile("cp.async.commit_group;\n" ::: "memory");
}
template <int N>
__device__ __forceinline__ void cp_wait() {
    asm volatile("cp.async.wait_group %0;\n" :: "n"(N) : "memory");
}

__global__ void __launch_bounds__(THREADS, 1)
tsb_kernel(const float* __restrict__ x, const float* __restrict__ alpha_p,
           const float* __restrict__ beta_p, float* __restrict__ out) {
    extern __shared__ float smem[];
    float* aX = smem + WARPS * WIN_F;     // alpha * x[0, t]

    const int tid  = threadIdx.x;
    const int wid  = tid >> 5;
    const int lane = tid & 31;
    const float alpha  = __ldg(alpha_p);
    const float beta   = __ldg(beta_p);
    const float omb    = 1.0f - beta;
    const float nalpha = -alpha;

    // One-time staging of the global level-driver sequence
#pragma no_unroll
    for (int i = tid; i < T_LEN / 4; i += THREADS) {
        float4 v = __ldg(reinterpret_cast<const float4*>(x) + i);
        v.x *= alpha; v.y *= alpha; v.z *= alpha; v.w *= alpha;
        reinterpret_cast<float4*>(aX)[i] = v;
    }
    __syncthreads();   // ONLY CTA barrier

    const int chunk  = wid & 3;            // 0..3 T-chunk
    const int rowgrp = wid >> 2;           // 0..1
    const int t_start = CHUNK_START_C[chunk];
    const int t_load0 = (chunk == 0) ? 0 : t_start - WARM;
    const int warm_tl = (chunk == 0) ? 0 : WARM_TILES;

    const int row_base = blockIdx.x * ROWS + rowgrp * WROWS;
    float* wbuf = smem + wid * WIN_F;
    const uint32_t wbuf_sa = (uint32_t)__cvta_generic_to_shared(wbuf);
    const float* xbase = x + (size_t)row_base * T_LEN + t_load0;
    float* obase = out + (size_t)row_base * T_LEN + t_load0;

    // Per-warp tile load: coalesced global (2 rows x 256B per instr -> 4 lines),
    // XOR-swizzled smem destination (conflict-free for compute LDS.128).
    auto load_tile = [&](int tile, int slot) {
        uint32_t sbase = wbuf_sa + (uint32_t)(slot * TILE_F) * 4u;
#pragma unroll
        for (int i = 0; i < 16; ++i) {
            int idx = lane + 32 * i;       // 0..511 (32 rows x 16 float4)
            int row = idx >> 4;
            int j4  = idx & 15;
            int js  = j4 ^ (row & 7);
            const float* src = xbase + (size_t)row * T_LEN + tile * TT + j4 * 4;
            cp_async16(sbase + (uint32_t)(row * TT + js * 4) * 4u, src);
        }
    };

    // Prologue: fill the 2-deep ring
#pragma unroll
    for (int k = 0; k < STAGES; ++k) {
        load_tile(k, k);
        cp_commit();
    }

    float A = 0.0f, Bs = 0.0f;
    const int swz = lane & 7;

#define TSB_STEP(xval, aval, oval)                      \
    {                                                   \
        float nz  = fminf(fabsf(xval), 1.0f);           \
        float bnz = fminf(fabsf(xval), beta);           \
        float t1  = fmaf(nalpha, A, aval);              \
        float Bn  = fmaf(nz, t1, A);                    \
        float An  = fmaf(Bs, omb, bnz);                 \
        oval = An * Bn; A = An; Bs = Bn;                \
    }

    for (int tile = 0; tile < N_TILES; ++tile) {
        cp_wait<STAGES - 1>();   // per-thread cp.async group state

        const int slot = tile % STAGES;
        float* slot_base = wbuf + slot * TILE_F;
        float* xr = slot_base + lane * TT;   // lane's row; outputs go IN-PLACE
        const float* aXt = aX + t_load0 + tile * TT;
        const bool emit  = (tile >= warm_tl);

        // Compute 64 steps; each 16B chunk is read then overwritten by the
        // same lane with outputs (read-before-write within the thread).
#pragma unroll
        for (int j8 = 0; j8 < TT / 8; ++j8) {
            int j4a = (2 * j8) ^ swz;
            int j4b = j4a ^ 1;
            float4 xv0 = *reinterpret_cast<const float4*>(xr + j4a * 4);
            float4 xv1 = *reinterpret_cast<const float4*>(xr + j4b * 4);
            float4 av0 = *reinterpret_cast<const float4*>(aXt + j8 * 8);
            float4 av1 = *reinterpret_cast<const float4*>(aXt + j8 * 8 + 4);
            float4 o0, o1;
            TSB_STEP(xv0.x, av0.x, o0.x);
            TSB_STEP(xv0.y, av0.y, o0.y);
            TSB_STEP(xv0.z, av0.z, o0.z);
            TSB_STEP(xv0.w, av0.w, o0.w);
            TSB_STEP(xv1.x, av1.x, o1.x);
            TSB_STEP(xv1.y, av1.y, o1.y);
            TSB_STEP(xv1.z, av1.z, o1.z);
            TSB_STEP(xv1.w, av1.w, o1.w);
            *reinterpret_cast<float4*>(xr + j4a * 4) = o0;
            *reinterpret_cast<float4*>(xr + j4b * 4) = o1;
        }

        __syncwarp();   // all lanes' output STS visible before cross-lane readback

        if (emit) {
            // Coalesced store: mirror of load pattern (4 lines per STG.128)
#pragma unroll
            for (int i = 0; i < 16; ++i) {
                int idx = lane + 32 * i;
                int row = idx >> 4;
                int j4  = idx & 15;
                int js  = j4 ^ (row & 7);
                float4 v = *reinterpret_cast<const float4*>(
                    slot_base + row * TT + js * 4);
                *reinterpret_cast<float4*>(
                    obase + (size_t)row * T_LEN + tile * TT + j4 * 4) = v;
            }
        }

        __syncwarp();   // readback done before refill cp.async is issued

        // Refill the slot just consumed (program order: LDS above precede
        // these async smem writes)
        int nt = tile + STAGES;
        if (nt < N_TILES)
            load_tile(nt, slot);
        cp_commit();   // always commit: keeps wait_group accounting aligned
    }
#undef TSB_STEP
}

extern "C" void kernel_launch(void* const* d_in, const int* in_sizes, int n_in,
                              void* d_out, int out_size) {
    const float* x       = (const float*)d_in[0];   // (B, T, 1) float32
    const float* alpha_p = (const float*)d_in[1];   // (1, 1)
    const float* beta_p  = (const float*)d_in[2];   // (1, 1)
    float* out = (float*)d_out;

    int batch = in_sizes[0] / T_LEN;                // 8192
    int grid  = batch / ROWS;                       // 128 CTAs -> one wave

    cudaFuncSetAttribute(tsb_kernel, cudaFuncAttributeMaxDynamicSharedMemorySize,
                         SMEM_BYTES);
    tsb_kernel<<<grid, THREADS, SMEM_BYTES>>>(x, alpha_p, beta_p, out);
}

// round 14
// speedup vs baseline: 1.0616x; 1.0616x over previous
#include <cuda_runtime.h>
#include <cstdint>

// TSBRNN: B=8192 rows, T=4096, per-row 2-state swap recurrence.
// R14: TT=128 tiles (512B contiguous per row per DRAM page visit, for both
// reads and writes) + 2-way T split (warmup traffic 24MB -> 8MB; 264MB total).
// 4 warps/CTA (one per SMSP), uniform 17 tiles/warp, 2-stage in-place ring,
// smem 144KB, grid 128 = one wave. Loads/stores: 1 instr = 1 row x 512B.

namespace {
constexpr int T_LEN   = 4096;
constexpr int TT      = 128;              // timesteps per tile (512B per row)
constexpr int WROWS   = 32;               // rows per warp (1 row/lane)
constexpr int WARPS   = 4;                // 2 rowgroups x 2 T-chunks
constexpr int THREADS = 32 * WARPS;       // 128
constexpr int ROWS    = 64;               // rows per CTA -> grid 128 (one wave)
constexpr int STAGES  = 2;
constexpr int TILE_F  = WROWS * TT;       // 4096 floats = 16KB per stage
constexpr int WIN_F   = STAGES * TILE_F;  // 32KB ring per warp
constexpr int SMEM_FLOATS = WARPS * WIN_F + T_LEN;
constexpr int SMEM_BYTES  = SMEM_FLOATS * 4;   // 128KB + 16KB = 144KB
constexpr int WARM       = 256;           // warmup steps, chunk 1 (2 tiles)
constexpr int E0         = 2176;          // chunk-0 emit length (17 tiles)
constexpr int N_TILES    = 17;            // uniform tiles per warp
constexpr int WARM_TILES = WARM / TT;     // 2
}

__device__ __forceinline__ void cp_async16(uint32_t dst, const void* src) {
    asm volatile("cp.async.cg.shared.global [%0], [%1], 16;\n" :: "r"(dst), "l"(src));
}
__device__ __forceinline__ void cp_commit() {
    asm volatile("cp.async.commit_group;\n" ::: "memory");
}
template <int N>
__device__ __forceinline__ void cp_wait() {
    asm volatile("cp.async.wait_group %0;\n" :: "n"(N) : "memory");
}

__global__ void __launch_bounds__(THREADS, 1)
tsb_kernel(const float* __restrict__ x, const float* __restrict__ alpha_p,
           const float* __restrict__ beta_p, float* __restrict__ out) {
    extern __shared__ float smem[];
    float* aX = smem + WARPS * WIN_F;     // alpha * x[0, t]

    const int tid  = threadIdx.x;
    const int wid  = tid >> 5;
    const int lane = tid & 31;
    const float alpha  = __ldg(alpha_p);
    const float beta   = __ldg(beta_p);
    const float omb    = 1.0f - beta;
    const float nalpha = -alpha;

    // One-time staging of the global level-driver sequence
#pragma no_unroll
    for (int i = tid; i < T_LEN / 4; i += THREADS) {
        float4 v = __ldg(reinterpret_cast<const float4*>(x) + i);
        v.x *= alpha; v.y *= alpha; v.z *= alpha; v.w *= alpha;
        reinterpret_cast<float4*>(aX)[i] = v;
    }
    __syncthreads();   // ONLY CTA barrier

    const int chunk  = wid & 1;            // 0..1 T-chunk
    const int rowgrp = wid >> 1;           // 0..1 row group
    // Chunk 0: emits [0, 2176). Chunk 1: loads from 1920, warms 2 tiles,
    // emits [2176, 4096). Both run exactly 17 tiles.
    const int t_load0 = (chunk == 0) ? 0 : (E0 - WARM);   // 0 or 1920
    const int warm_tl = (chunk == 0) ? 0 : WARM_TILES;

    const int row_base = blockIdx.x * ROWS + rowgrp * WROWS;
    float* wbuf = smem + wid * WIN_F;
    const uint32_t wbuf_sa = (uint32_t)__cvta_generic_to_shared(wbuf);
    const float* xbase = x + (size_t)row_base * T_LEN + t_load0;
    float* obase = out + (size_t)row_base * T_LEN + t_load0;

    // Tile load: instruction i = row i's full 512B segment (32 lanes x 16B,
    // 4 lines, contiguous). Smem dst XOR-swizzled (conflict-free LDS.128).
    auto load_tile = [&](int tile, int slot) {
        uint32_t sbase = wbuf_sa + (uint32_t)(slot * TILE_F) * 4u;
#pragma unroll
        for (int i = 0; i < 32; ++i) {     // one row per instruction
            int js = lane ^ (i & 7);
            const float* src = xbase + (size_t)i * T_LEN + tile * TT + lane * 4;
            cp_async16(sbase + (uint32_t)(i * TT + js * 4) * 4u, src);
        }
    };

    // Prologue: fill the 2-deep ring
#pragma unroll
    for (int k = 0; k < STAGES; ++k) {
        load_tile(k, k);
        cp_commit();
    }

    float A = 0.0f, Bs = 0.0f;
    const int swz = lane & 7;

#define TSB_STEP(xval, aval, oval)                      \
    {                                                   \
        float nz  = fminf(fabsf(xval), 1.0f);           \
        float bnz = fminf(fabsf(xval), beta);           \
        float t1  = fmaf(nalpha, A, aval);              \
        float Bn  = fmaf(nz, t1, A);                    \
        float An  = fmaf(Bs, omb, bnz);                 \
        oval = An * Bn; A = An; Bs = Bn;                \
    }

    for (int tile = 0; tile < N_TILES; ++tile) {
        cp_wait<STAGES - 1>();   // per-thread cp.async group state

        const int slot = tile % STAGES;
        float* slot_base = wbuf + slot * TILE_F;
        float* xr = slot_base + lane * TT;   // lane's row; outputs go IN-PLACE
        const float* aXt = aX + t_load0 + tile * TT;
        const bool emit  = (tile >= warm_tl);

        // Compute 128 steps; each 16B chunk is read then overwritten by the
        // same lane with outputs (read-before-write within the thread).
#pragma unroll
        for (int j8 = 0; j8 < TT / 8; ++j8) {
            int j4a = (2 * j8) ^ swz;      // 0..31, swizzle flips low 3 bits
            int j4b = j4a ^ 1;
            float4 xv0 = *reinterpret_cast<const float4*>(xr + j4a * 4);
            float4 xv1 = *reinterpret_cast<const float4*>(xr + j4b * 4);
            float4 av0 = *reinterpret_cast<const float4*>(aXt + j8 * 8);
            float4 av1 = *reinterpret_cast<const float4*>(aXt + j8 * 8 + 4);
            float4 o0, o1;
            TSB_STEP(xv0.x, av0.x, o0.x);
            TSB_STEP(xv0.y, av0.y, o0.y);
            TSB_STEP(xv0.z, av0.z, o0.z);
            TSB_STEP(xv0.w, av0.w, o0.w);
            TSB_STEP(xv1.x, av1.x, o1.x);
            TSB_STEP(xv1.y, av1.y, o1.y);
            TSB_STEP(xv1.z, av1.z, o1.z);
            TSB_STEP(xv1.w, av1.w, o1.w);
            *reinterpret_cast<float4*>(xr + j4a * 4) = o0;
            *reinterpret_cast<float4*>(xr + j4b * 4) = o1;
        }

        __syncwarp();   // all lanes' output STS visible before cross-lane readback

        if (emit) {
            // Coalesced store: instruction i = row i's full 512B segment
#pragma unroll
            for (int i = 0; i < 32; ++i) {
                int js = lane ^ (i & 7);
                float4 v = *reinterpret_cast<const float4*>(
                    slot_base + i * TT + js * 4);
                *reinterpret_cast<float4*>(
                    obase + (size_t)i * T_LEN + tile * TT + lane * 4) = v;
            }
        }

        __syncwarp();   // readback done before refill cp.async is issued

        // Refill the slot just consumed (program order: LDS above precede
        // these async smem writes)
        int nt = tile + STAGES;
        if (nt < N_TILES)
            load_tile(nt, slot);
        cp_commit();   // always commit: keeps wait_group accounting aligned
    }
#undef TSB_STEP
}

extern "C" void kernel_launch(void* const* d_in, const int* in_sizes, int n_in,
                              void* d_out, int out_size) {
    const float* x       = (const float*)d_in[0];   // (B, T, 1) float32
    const float* alpha_p = (const float*)d_in[1];   // (1, 1)
    const float* beta_p  = (const float*)d_in[2];   // (1, 1)
    float* out = (float*)d_out;

    int batch = in_sizes[0] / T_LEN;                // 8192
    int grid  = batch / ROWS;                       // 128 CTAs -> one wave

    cudaFuncSetAttribute(tsb_kernel, cudaFuncAttributeMaxDynamicSharedMemorySize,
                         SMEM_BYTES);
    tsb_kernel<<<grid, THREADS, SMEM_BYTES>>>(x, alpha_p, beta_p, out);
}